// round 6
// baseline (speedup 1.0000x reference)
#include <cuda_runtime.h>

// VoxelBracketPredictor_v2 — 4-kernel pipeline:
//  k0 bounds: segment boundaries (int4 scan of sorted segment_ids)
//  k1 group:  class-sort of samples + 16-sample CTA descriptors (1 CTA)
//  k2 pool:   mean-pool, TWO warps per sample (1024 CTAs) -> high DRAM occupancy
//  k3 mlp:    16 same-class samples per CTA; ALL layers CTA-cooperative
//             (coarse + the single routed refinement head) -> minimal L2 weight traffic

#define EPS 1e-5f
#define BMAX 4096
#define MAXCTA 264

__device__ int   g_bound[BMAX + 1];
__device__ float g_pooled[BMAX * 96];
__device__ int   g_order[BMAX];
__device__ int   g_ctaK[MAXCTA];
__device__ int   g_ctaBase[MAXCTA];
__device__ int   g_ctaCnt[MAXCTA];

// ---------------- kernel 0: boundaries ----------------
__global__ void bounds_kernel(const int* __restrict__ seg, int N, int B) {
    int t = blockIdx.x * blockDim.x + threadIdx.x;
    int i = t * 4;
    if (i >= N) return;
    int vals[4];
    if (i + 4 <= N) {
        int4 v = *(const int4*)(seg + i);
        vals[0] = v.x; vals[1] = v.y; vals[2] = v.z; vals[3] = v.w;
    } else {
        for (int j = 0; j < 4; j++) vals[j] = (i + j < N) ? seg[i + j] : vals[j > 0 ? j - 1 : 0];
    }
    int prev = (i == 0) ? -1 : seg[i - 1];
    int lim = min(4, N - i);
    for (int j = 0; j < lim; j++) {
        int cur = vals[j];
        for (int b = prev + 1; b <= cur; b++) g_bound[b] = i + j;
        prev = cur;
    }
    if (i + 4 >= N)
        for (int b = prev + 1; b <= B; b++) g_bound[b] = N;
}

// ---------------- kernel 1: class grouping + CTA descriptors (1 CTA) -------
__global__ __launch_bounds__(256) void group_kernel(const int* __restrict__ cls, int B) {
    __shared__ short scls[BMAX];
    __shared__ int scnt[4][256];
    __shared__ int sbase[4];
    const int tid = threadIdx.x;

    for (int i = tid; i < B; i += 256) scls[i] = (short)cls[i];
    __syncthreads();

    const int chunk = (B + 255) / 256;
    const int lo = tid * chunk, hi = min(lo + chunk, B);
    int c[4] = {0, 0, 0, 0};
    for (int i = lo; i < hi; i++) c[scls[i]]++;
#pragma unroll
    for (int k = 0; k < 4; k++) scnt[k][tid] = c[k];
    __syncthreads();

    int pre[4] = {0, 0, 0, 0};
    for (int j = 0; j < tid; j++)
#pragma unroll
        for (int k = 0; k < 4; k++) pre[k] += scnt[k][j];

    if (tid == 255) {
        int tot[4];
#pragma unroll
        for (int k = 0; k < 4; k++) tot[k] = pre[k] + c[k];
        int b0 = 0;
#pragma unroll
        for (int k = 0; k < 4; k++) { sbase[k] = b0; b0 += tot[k]; }
        int ci = 0;
        for (int k = 0; k < 4; k++) {
            int base = sbase[k];
            for (int off = 0; off < tot[k]; off += 16) {
                g_ctaK[ci] = k;
                g_ctaBase[ci] = base + off;
                g_ctaCnt[ci] = min(16, tot[k] - off);
                ci++;
            }
        }
        for (; ci < MAXCTA; ci++) g_ctaK[ci] = -1;
    }
    __syncthreads();

    int pos[4];
#pragma unroll
    for (int k = 0; k < 4; k++) pos[k] = sbase[k] + pre[k];
    for (int i = lo; i < hi; i++) { int k = scls[i]; g_order[pos[k]++] = i; }
}

// ---------------- kernel 2: pooling, 2 warps per sample ----------------
__global__ __launch_bounds__(256) void pool_kernel(const float* __restrict__ feat, int B) {
    __shared__ float4 spart[8][4][24];
    __shared__ float  spool[8][96];
    __shared__ float  sinv[4];
    const int tid = threadIdx.x, lane = tid & 31, w = tid >> 5;
    const int p = w >> 1, h = w & 1;
    const int b = blockIdx.x * 4 + p;
    const bool valid = b < B;

    if (valid) {
        const int start = g_bound[b], end = g_bound[b + 1];
        const int nrows = end - start;
        if (h == 0 && lane == 0) sinv[p] = 1.f / fmaxf((float)nrows, 1.f);
        const int half0 = nrows >> 1;
        const int rlo = h ? half0 : 0;
        const int myn = h ? (nrows - half0) : half0;
        const float* base = feat + (size_t)(start + rlo) * 96;

        const int i0 = lane, i1 = lane + 32, i2 = lane + 64;
        const int ro0 = i0 / 24, ro1 = i1 / 24, ro2 = i2 / 24;
        const int co0 = 4 * (i0 % 24), co1 = 4 * (i1 % 24), co2 = 4 * (i2 % 24);
        const float* p0 = base + ro0 * 96 + co0;
        const float* p1 = base + ro1 * 96 + co1;
        const float* p2 = base + ro2 * 96 + co2;

        float4 a0 = make_float4(0.f, 0.f, 0.f, 0.f), a1 = a0, a2 = a0;
        int r0 = 0;
        for (; r0 + 16 <= myn; r0 += 16) {
            float4 v0 = *(const float4*)(p0 + (size_t)(r0 +  0) * 96);
            float4 v1 = *(const float4*)(p1 + (size_t)(r0 +  0) * 96);
            float4 v2 = *(const float4*)(p2 + (size_t)(r0 +  0) * 96);
            float4 v3 = *(const float4*)(p0 + (size_t)(r0 +  4) * 96);
            float4 v4 = *(const float4*)(p1 + (size_t)(r0 +  4) * 96);
            float4 v5 = *(const float4*)(p2 + (size_t)(r0 +  4) * 96);
            float4 v6 = *(const float4*)(p0 + (size_t)(r0 +  8) * 96);
            float4 v7 = *(const float4*)(p1 + (size_t)(r0 +  8) * 96);
            float4 v8 = *(const float4*)(p2 + (size_t)(r0 +  8) * 96);
            float4 v9 = *(const float4*)(p0 + (size_t)(r0 + 12) * 96);
            float4 va = *(const float4*)(p1 + (size_t)(r0 + 12) * 96);
            float4 vb = *(const float4*)(p2 + (size_t)(r0 + 12) * 96);
            a0.x += v0.x; a0.y += v0.y; a0.z += v0.z; a0.w += v0.w;
            a1.x += v1.x; a1.y += v1.y; a1.z += v1.z; a1.w += v1.w;
            a2.x += v2.x; a2.y += v2.y; a2.z += v2.z; a2.w += v2.w;
            a0.x += v3.x; a0.y += v3.y; a0.z += v3.z; a0.w += v3.w;
            a1.x += v4.x; a1.y += v4.y; a1.z += v4.z; a1.w += v4.w;
            a2.x += v5.x; a2.y += v5.y; a2.z += v5.z; a2.w += v5.w;
            a0.x += v6.x; a0.y += v6.y; a0.z += v6.z; a0.w += v6.w;
            a1.x += v7.x; a1.y += v7.y; a1.z += v7.z; a1.w += v7.w;
            a2.x += v8.x; a2.y += v8.y; a2.z += v8.z; a2.w += v8.w;
            a0.x += v9.x; a0.y += v9.y; a0.z += v9.z; a0.w += v9.w;
            a1.x += va.x; a1.y += va.y; a1.z += va.z; a1.w += va.w;
            a2.x += vb.x; a2.y += vb.y; a2.z += vb.z; a2.w += vb.w;
        }
        for (; r0 + 8 <= myn; r0 += 8) {
            float4 v0 = *(const float4*)(p0 + (size_t)r0 * 96);
            float4 v1 = *(const float4*)(p1 + (size_t)r0 * 96);
            float4 v2 = *(const float4*)(p2 + (size_t)r0 * 96);
            float4 v3 = *(const float4*)(p0 + (size_t)(r0 + 4) * 96);
            float4 v4 = *(const float4*)(p1 + (size_t)(r0 + 4) * 96);
            float4 v5 = *(const float4*)(p2 + (size_t)(r0 + 4) * 96);
            a0.x += v0.x; a0.y += v0.y; a0.z += v0.z; a0.w += v0.w;
            a1.x += v1.x; a1.y += v1.y; a1.z += v1.z; a1.w += v1.w;
            a2.x += v2.x; a2.y += v2.y; a2.z += v2.z; a2.w += v2.w;
            a0.x += v3.x; a0.y += v3.y; a0.z += v3.z; a0.w += v3.w;
            a1.x += v4.x; a1.y += v4.y; a1.z += v4.z; a1.w += v4.w;
            a2.x += v5.x; a2.y += v5.y; a2.z += v5.z; a2.w += v5.w;
        }
        for (; r0 < myn; r0 += 4) {
            if (r0 + ro0 < myn) {
                float4 v = *(const float4*)(p0 + (size_t)r0 * 96);
                a0.x += v.x; a0.y += v.y; a0.z += v.z; a0.w += v.w;
            }
            if (r0 + ro1 < myn) {
                float4 v = *(const float4*)(p1 + (size_t)r0 * 96);
                a1.x += v.x; a1.y += v.y; a1.z += v.z; a1.w += v.w;
            }
            if (r0 + ro2 < myn) {
                float4 v = *(const float4*)(p2 + (size_t)r0 * 96);
                a2.x += v.x; a2.y += v.y; a2.z += v.z; a2.w += v.w;
            }
        }
        spart[w][ro0][co0 >> 2] = a0;
        spart[w][ro1][co1 >> 2] = a1;
        spart[w][ro2][co2 >> 2] = a2;
        __syncwarp();

        const float* sp = (const float*)&spart[w][0][0];
#pragma unroll
        for (int j = 0; j < 3; j++) {
            int c = lane + j * 32;
            spool[w][c] = sp[c] + sp[96 + c] + sp[192 + c] + sp[288 + c];
        }
    }
    __syncthreads();

    for (int idx = tid; idx < 384; idx += 256) {
        int pp = idx / 96, c = idx - 96 * pp;
        int bb = blockIdx.x * 4 + pp;
        if (bb < B)
            g_pooled[bb * 96 + c] = (spool[2 * pp][c] + spool[2 * pp + 1][c]) * sinv[pp];
    }
}

// ---------------- kernel 3: grouped MLP, all layers CTA-cooperative --------
__device__ __forceinline__ float warpSum(float v) {
#pragma unroll
    for (int o = 16; o; o >>= 1) v += __shfl_xor_sync(0xffffffffu, v, o);
    return v;
}

__global__ __launch_bounds__(256) void mlp_kernel(
    const float* __restrict__ cW1, const float* __restrict__ cb1,
    const float* __restrict__ cg1, const float* __restrict__ cbe1,
    const float* __restrict__ cW2, const float* __restrict__ cb2,
    const float* __restrict__ cg2, const float* __restrict__ cbe2,
    const float* __restrict__ cW3, const float* __restrict__ cb3,
    const float* __restrict__ rW1, const float* __restrict__ rb1,
    const float* __restrict__ rg1, const float* __restrict__ rbe1,
    const float* __restrict__ rW2, const float* __restrict__ rb2,
    const float* __restrict__ rg2, const float* __restrict__ rbe2,
    const float* __restrict__ rW3, const float* __restrict__ rb3,
    float* __restrict__ out)
{
    const int k = g_ctaK[blockIdx.x];
    if (k < 0) return;
    const int base = g_ctaBase[blockIdx.x];
    const int cnt  = g_ctaCnt[blockIdx.x];

    __shared__ int   sidx[16];
    __shared__ float sp[16][96];
    __shared__ float actA[16][256];
    __shared__ float actB[16][128];
    __shared__ float sstat[16][2];
    __shared__ float scoarse[16][3];

    const int tid = threadIdx.x, lane = tid & 31, w = tid >> 5;
    if (tid < 16) sidx[tid] = g_order[base + min(tid, cnt - 1)];
    __syncthreads();

    for (int idx = tid; idx < 16 * 96; idx += 256) {
        int s = idx / 96, c = idx - 96 * s;
        sp[s][c] = g_pooled[sidx[s] * 96 + c];
    }
    __syncthreads();

    const int s0 = 2 * w, s1 = 2 * w + 1;

    // ===== coarse L1: 96 -> 256 (thread owns feature tid for all 16 samples) =====
    float acc[16];
    {
        const int f = tid;
        const float bv = cb1[f];
#pragma unroll
        for (int s = 0; s < 16; s++) acc[s] = bv;
        for (int c = 0; c < 96; c += 4) {
            float w0 = cW1[(c + 0) * 256 + f];
            float w1 = cW1[(c + 1) * 256 + f];
            float w2 = cW1[(c + 2) * 256 + f];
            float w3 = cW1[(c + 3) * 256 + f];
#pragma unroll
            for (int s = 0; s < 16; s++) {
                float4 x = *(const float4*)(&sp[s][c]);
                acc[s] = fmaf(x.x, w0, acc[s]);
                acc[s] = fmaf(x.y, w1, acc[s]);
                acc[s] = fmaf(x.z, w2, acc[s]);
                acc[s] = fmaf(x.w, w3, acc[s]);
            }
        }
#pragma unroll
        for (int s = 0; s < 16; s++) actA[s][tid] = acc[s];
    }
    __syncthreads();
    {   // LN stats over 256 features; warp w -> samples s0, s1
        float su0 = 0.f, sq0 = 0.f, su1 = 0.f, sq1 = 0.f;
#pragma unroll
        for (int j = 0; j < 8; j++) {
            float x0 = actA[s0][lane + 32 * j];
            float x1 = actA[s1][lane + 32 * j];
            su0 += x0; sq0 = fmaf(x0, x0, sq0);
            su1 += x1; sq1 = fmaf(x1, x1, sq1);
        }
        su0 = warpSum(su0); sq0 = warpSum(sq0);
        su1 = warpSum(su1); sq1 = warpSum(sq1);
        if (lane == 0) {
            float m = su0 * (1.f / 256.f);
            sstat[s0][0] = m; sstat[s0][1] = rsqrtf(sq0 * (1.f / 256.f) - m * m + EPS);
            m = su1 * (1.f / 256.f);
            sstat[s1][0] = m; sstat[s1][1] = rsqrtf(sq1 * (1.f / 256.f) - m * m + EPS);
        }
    }
    __syncthreads();
    {
        const float g = cg1[tid], e = cbe1[tid];
#pragma unroll
        for (int s = 0; s < 16; s++)
            actA[s][tid] = fmaxf(fmaf((acc[s] - sstat[s][0]) * sstat[s][1], g, e), 0.f);
    }
    __syncthreads();

    // ===== coarse L2: 256 -> 128 (two thread-halves, 8 samples each) =====
    float acc2[8];
    const int fB = tid & 127, hf = tid >> 7;
    {
        const float bv = cb2[fB];
#pragma unroll
        for (int i = 0; i < 8; i++) acc2[i] = bv;
        for (int c = 0; c < 256; c += 4) {
            float w0 = cW2[(c + 0) * 128 + fB];
            float w1 = cW2[(c + 1) * 128 + fB];
            float w2 = cW2[(c + 2) * 128 + fB];
            float w3 = cW2[(c + 3) * 128 + fB];
#pragma unroll
            for (int i = 0; i < 8; i++) {
                float4 x = *(const float4*)(&actA[hf * 8 + i][c]);
                acc2[i] = fmaf(x.x, w0, acc2[i]);
                acc2[i] = fmaf(x.y, w1, acc2[i]);
                acc2[i] = fmaf(x.z, w2, acc2[i]);
                acc2[i] = fmaf(x.w, w3, acc2[i]);
            }
        }
#pragma unroll
        for (int i = 0; i < 8; i++) actB[hf * 8 + i][fB] = acc2[i];
    }
    __syncthreads();
    {   // LN stats over 128 features
        float su0 = 0.f, sq0 = 0.f, su1 = 0.f, sq1 = 0.f;
#pragma unroll
        for (int j = 0; j < 4; j++) {
            float x0 = actB[s0][lane + 32 * j];
            float x1 = actB[s1][lane + 32 * j];
            su0 += x0; sq0 = fmaf(x0, x0, sq0);
            su1 += x1; sq1 = fmaf(x1, x1, sq1);
        }
        su0 = warpSum(su0); sq0 = warpSum(sq0);
        su1 = warpSum(su1); sq1 = warpSum(sq1);
        if (lane == 0) {
            float m = su0 * (1.f / 128.f);
            sstat[s0][0] = m; sstat[s0][1] = rsqrtf(sq0 * (1.f / 128.f) - m * m + EPS);
            m = su1 * (1.f / 128.f);
            sstat[s1][0] = m; sstat[s1][1] = rsqrtf(sq1 * (1.f / 128.f) - m * m + EPS);
        }
    }
    __syncthreads();
    {
        const float g = cg2[fB], e = cbe2[fB];
#pragma unroll
        for (int i = 0; i < 8; i++) {
            int s = hf * 8 + i;
            actB[s][fB] = fmaxf(fmaf((acc2[i] - sstat[s][0]) * sstat[s][1], g, e), 0.f);
        }
    }
    __syncthreads();

    // ===== coarse L3: 128 -> 3 (warp w -> samples s0, s1) =====
    {
        float q00 = 0.f, q01 = 0.f, q02 = 0.f, q10 = 0.f, q11 = 0.f, q12 = 0.f;
#pragma unroll
        for (int t = 0; t < 4; t++) {
            int c = lane + 32 * t;
            float w0 = cW3[c * 3 + 0], w1 = cW3[c * 3 + 1], w2 = cW3[c * 3 + 2];
            float x0 = actB[s0][c], x1 = actB[s1][c];
            q00 = fmaf(x0, w0, q00); q01 = fmaf(x0, w1, q01); q02 = fmaf(x0, w2, q02);
            q10 = fmaf(x1, w0, q10); q11 = fmaf(x1, w1, q11); q12 = fmaf(x1, w2, q12);
        }
        q00 = warpSum(q00); q01 = warpSum(q01); q02 = warpSum(q02);
        q10 = warpSum(q10); q11 = warpSum(q11); q12 = warpSum(q12);
        if (lane == 0) {
            scoarse[s0][0] = q00 + cb3[0]; scoarse[s0][1] = q01 + cb3[1]; scoarse[s0][2] = q02 + cb3[2];
            scoarse[s1][0] = q10 + cb3[0]; scoarse[s1][1] = q11 + cb3[1]; scoarse[s1][2] = q12 + cb3[2];
        }
    }
    __syncthreads();

    // ===== refine L1: 96 -> 128, head k (CTA-cooperative, overwrite actB) =====
    {
        const float* W = rW1 + k * 96 * 128;
        const float bv = rb1[k * 128 + fB];
#pragma unroll
        for (int i = 0; i < 8; i++) acc2[i] = bv;
        for (int c = 0; c < 96; c += 4) {
            float w0 = W[(c + 0) * 128 + fB];
            float w1 = W[(c + 1) * 128 + fB];
            float w2 = W[(c + 2) * 128 + fB];
            float w3 = W[(c + 3) * 128 + fB];
#pragma unroll
            for (int i = 0; i < 8; i++) {
                float4 x = *(const float4*)(&sp[hf * 8 + i][c]);
                acc2[i] = fmaf(x.x, w0, acc2[i]);
                acc2[i] = fmaf(x.y, w1, acc2[i]);
                acc2[i] = fmaf(x.z, w2, acc2[i]);
                acc2[i] = fmaf(x.w, w3, acc2[i]);
            }
        }
#pragma unroll
        for (int i = 0; i < 8; i++) actB[hf * 8 + i][fB] = acc2[i];
    }
    __syncthreads();
    {   // LN stats over 128 features
        float su0 = 0.f, sq0 = 0.f, su1 = 0.f, sq1 = 0.f;
#pragma unroll
        for (int j = 0; j < 4; j++) {
            float x0 = actB[s0][lane + 32 * j];
            float x1 = actB[s1][lane + 32 * j];
            su0 += x0; sq0 = fmaf(x0, x0, sq0);
            su1 += x1; sq1 = fmaf(x1, x1, sq1);
        }
        su0 = warpSum(su0); sq0 = warpSum(sq0);
        su1 = warpSum(su1); sq1 = warpSum(sq1);
        if (lane == 0) {
            float m = su0 * (1.f / 128.f);
            sstat[s0][0] = m; sstat[s0][1] = rsqrtf(sq0 * (1.f / 128.f) - m * m + EPS);
            m = su1 * (1.f / 128.f);
            sstat[s1][0] = m; sstat[s1][1] = rsqrtf(sq1 * (1.f / 128.f) - m * m + EPS);
        }
    }
    __syncthreads();
    {
        const float g = rg1[k * 128 + fB], e = rbe1[k * 128 + fB];
#pragma unroll
        for (int i = 0; i < 8; i++) {
            int s = hf * 8 + i;
            actB[s][fB] = fmaxf(fmaf((acc2[i] - sstat[s][0]) * sstat[s][1], g, e), 0.f);
        }
    }
    __syncthreads();

    // ===== refine L2: 128 -> 64 (four thread-quarters, 4 samples each) =====
    float acc3[4];
    const int fC = tid & 63, qf = tid >> 6;
    {
        const float* W = rW2 + k * 128 * 64;
        const float bv = rb2[k * 64 + fC];
#pragma unroll
        for (int i = 0; i < 4; i++) acc3[i] = bv;
        for (int c = 0; c < 128; c += 4) {
            float w0 = W[(c + 0) * 64 + fC];
            float w1 = W[(c + 1) * 64 + fC];
            float w2 = W[(c + 2) * 64 + fC];
            float w3 = W[(c + 3) * 64 + fC];
#pragma unroll
            for (int i = 0; i < 4; i++) {
                float4 x = *(const float4*)(&actB[qf * 4 + i][c]);
                acc3[i] = fmaf(x.x, w0, acc3[i]);
                acc3[i] = fmaf(x.y, w1, acc3[i]);
                acc3[i] = fmaf(x.z, w2, acc3[i]);
                acc3[i] = fmaf(x.w, w3, acc3[i]);
            }
        }
#pragma unroll
        for (int i = 0; i < 4; i++) actA[qf * 4 + i][fC] = acc3[i];
    }
    __syncthreads();
    {   // LN stats over 64 features
        float su0 = 0.f, sq0 = 0.f, su1 = 0.f, sq1 = 0.f;
#pragma unroll
        for (int j = 0; j < 2; j++) {
            float x0 = actA[s0][lane + 32 * j];
            float x1 = actA[s1][lane + 32 * j];
            su0 += x0; sq0 = fmaf(x0, x0, sq0);
            su1 += x1; sq1 = fmaf(x1, x1, sq1);
        }
        su0 = warpSum(su0); sq0 = warpSum(sq0);
        su1 = warpSum(su1); sq1 = warpSum(sq1);
        if (lane == 0) {
            float m = su0 * (1.f / 64.f);
            sstat[s0][0] = m; sstat[s0][1] = rsqrtf(sq0 * (1.f / 64.f) - m * m + EPS);
            m = su1 * (1.f / 64.f);
            sstat[s1][0] = m; sstat[s1][1] = rsqrtf(sq1 * (1.f / 64.f) - m * m + EPS);
        }
    }
    __syncthreads();
    {
        const float g = rg2[k * 64 + fC], e = rbe2[k * 64 + fC];
#pragma unroll
        for (int i = 0; i < 4; i++) {
            int s = qf * 4 + i;
            actA[s][fC] = fmaxf(fmaf((acc3[i] - sstat[s][0]) * sstat[s][1], g, e), 0.f);
        }
    }
    __syncthreads();

    // ===== refine L3: 64 -> 3, add coarse, write out (warp w -> s0, s1) =====
    {
        const float* W3 = rW3 + k * 192;
        float q00 = 0.f, q01 = 0.f, q02 = 0.f, q10 = 0.f, q11 = 0.f, q12 = 0.f;
#pragma unroll
        for (int t = 0; t < 2; t++) {
            int c = lane + 32 * t;
            float w0 = W3[c * 3 + 0], w1 = W3[c * 3 + 1], w2 = W3[c * 3 + 2];
            float x0 = actA[s0][c], x1 = actA[s1][c];
            q00 = fmaf(x0, w0, q00); q01 = fmaf(x0, w1, q01); q02 = fmaf(x0, w2, q02);
            q10 = fmaf(x1, w0, q10); q11 = fmaf(x1, w1, q11); q12 = fmaf(x1, w2, q12);
        }
        q00 = warpSum(q00); q01 = warpSum(q01); q02 = warpSum(q02);
        q10 = warpSum(q10); q11 = warpSum(q11); q12 = warpSum(q12);

        if (lane < 3) {
            float r0 = (lane == 0) ? q00 : (lane == 1) ? q01 : q02;
            float r1 = (lane == 0) ? q10 : (lane == 1) ? q11 : q12;
            float rb = rb3[k * 3 + lane];
            if (s0 < cnt) out[sidx[s0] * 3 + lane] = scoarse[s0][lane] + r0 + rb;
            if (s1 < cnt) out[sidx[s1] * 3 + lane] = scoarse[s1][lane] + r1 + rb;
        }
    }
}

// ---------------- launch ----------------
extern "C" void kernel_launch(void* const* d_in, const int* in_sizes, int n_in,
                              void* d_out, int out_size) {
    const float* feat = (const float*)d_in[0];
    const int*   seg  = (const int*)d_in[1];
    const int*   cls  = (const int*)d_in[2];
    const int N = in_sizes[1];
    const int B = in_sizes[2];

    bounds_kernel<<<(N / 4 + 255) / 256, 256>>>(seg, N, B);
    group_kernel<<<1, 256>>>(cls, B);
    pool_kernel<<<(B + 3) / 4, 256>>>(feat, B);
    mlp_kernel<<<MAXCTA, 256>>>(
        (const float*)d_in[3],  (const float*)d_in[4],  (const float*)d_in[5],  (const float*)d_in[6],
        (const float*)d_in[7],  (const float*)d_in[8],  (const float*)d_in[9],  (const float*)d_in[10],
        (const float*)d_in[11], (const float*)d_in[12],
        (const float*)d_in[13], (const float*)d_in[14], (const float*)d_in[15], (const float*)d_in[16],
        (const float*)d_in[17], (const float*)d_in[18], (const float*)d_in[19], (const float*)d_in[20],
        (const float*)d_in[21], (const float*)d_in[22],
        (float*)d_out);
}

// round 7
// speedup vs baseline: 1.1187x; 1.1187x over previous
#include <cuda_runtime.h>

// VoxelBracketPredictor_v2 — 3-kernel pipeline:
//  k0 bounds: segment boundaries (int4 scan of sorted segment_ids)
//  k1 group:  class-sort of samples + 8-sample same-class CTA descriptors (1 CTA)
//  k2 fused:  CTA = 8 SAME-CLASS samples, 512 threads.
//             pool (2 warps/sample, DRAM-bound) -> coarse MLP CTA-cooperative
//             -> ONE refinement head CTA-cooperative. MLP tail overlaps other
//             CTAs' pooling.

#define EPS 1e-5f
#define BMAX 4096
#define MAXCTA 520

__device__ int g_bound[BMAX + 1];
__device__ int g_order[BMAX];
__device__ int g_ctaK[MAXCTA];
__device__ int g_ctaBase[MAXCTA];
__device__ int g_ctaCnt[MAXCTA];

// ---------------- kernel 0: boundaries ----------------
__global__ void bounds_kernel(const int* __restrict__ seg, int N, int B) {
    int t = blockIdx.x * blockDim.x + threadIdx.x;
    int i = t * 4;
    if (i >= N) return;
    int vals[4];
    if (i + 4 <= N) {
        int4 v = *(const int4*)(seg + i);
        vals[0] = v.x; vals[1] = v.y; vals[2] = v.z; vals[3] = v.w;
    } else {
        for (int j = 0; j < 4; j++) vals[j] = (i + j < N) ? seg[i + j] : vals[j > 0 ? j - 1 : 0];
    }
    int prev = (i == 0) ? -1 : seg[i - 1];
    int lim = min(4, N - i);
    for (int j = 0; j < lim; j++) {
        int cur = vals[j];
        for (int b = prev + 1; b <= cur; b++) g_bound[b] = i + j;
        prev = cur;
    }
    if (i + 4 >= N)
        for (int b = prev + 1; b <= B; b++) g_bound[b] = N;
}

// ---------------- kernel 1: class grouping + 8-sample CTA descriptors ------
__global__ __launch_bounds__(256) void group_kernel(const int* __restrict__ cls, int B) {
    __shared__ short scls[BMAX];
    __shared__ int scnt[4][256];
    __shared__ int sbase[4];
    const int tid = threadIdx.x;

    for (int i = tid; i < B; i += 256) scls[i] = (short)cls[i];
    __syncthreads();

    const int chunk = (B + 255) / 256;
    const int lo = tid * chunk, hi = min(lo + chunk, B);
    int c[4] = {0, 0, 0, 0};
    for (int i = lo; i < hi; i++) c[scls[i]]++;
#pragma unroll
    for (int k = 0; k < 4; k++) scnt[k][tid] = c[k];
    __syncthreads();

    int pre[4] = {0, 0, 0, 0};
    for (int j = 0; j < tid; j++)
#pragma unroll
        for (int k = 0; k < 4; k++) pre[k] += scnt[k][j];

    if (tid == 255) {
        int tot[4];
#pragma unroll
        for (int k = 0; k < 4; k++) tot[k] = pre[k] + c[k];
        int b0 = 0;
#pragma unroll
        for (int k = 0; k < 4; k++) { sbase[k] = b0; b0 += tot[k]; }
        int ci = 0;
        for (int k = 0; k < 4; k++) {
            int base = sbase[k];
            for (int off = 0; off < tot[k]; off += 8) {
                g_ctaK[ci] = k;
                g_ctaBase[ci] = base + off;
                g_ctaCnt[ci] = min(8, tot[k] - off);
                ci++;
            }
        }
        for (; ci < MAXCTA; ci++) g_ctaK[ci] = -1;
    }
    __syncthreads();

    int pos[4];
#pragma unroll
    for (int k = 0; k < 4; k++) pos[k] = sbase[k] + pre[k];
    for (int i = lo; i < hi; i++) { int k = scls[i]; g_order[pos[k]++] = i; }
}

__device__ __forceinline__ float warpSum(float v) {
#pragma unroll
    for (int o = 16; o; o >>= 1) v += __shfl_xor_sync(0xffffffffu, v, o);
    return v;
}

// ---------------- kernel 2: fused pool + MLP (8 same-class samples) --------
__global__ __launch_bounds__(512, 2) void fused_kernel(
    const float* __restrict__ feat,
    const float* __restrict__ cW1, const float* __restrict__ cb1,
    const float* __restrict__ cg1, const float* __restrict__ cbe1,
    const float* __restrict__ cW2, const float* __restrict__ cb2,
    const float* __restrict__ cg2, const float* __restrict__ cbe2,
    const float* __restrict__ cW3, const float* __restrict__ cb3,
    const float* __restrict__ rW1, const float* __restrict__ rb1,
    const float* __restrict__ rg1, const float* __restrict__ rbe1,
    const float* __restrict__ rW2, const float* __restrict__ rb2,
    const float* __restrict__ rg2, const float* __restrict__ rbe2,
    const float* __restrict__ rW3, const float* __restrict__ rb3,
    float* __restrict__ out)
{
    const int k = g_ctaK[blockIdx.x];
    if (k < 0) return;
    const int base = g_ctaBase[blockIdx.x];
    const int cnt  = g_ctaCnt[blockIdx.x];

    __shared__ int    sidx[8];
    __shared__ float4 spart[16][4][24];  // per-warp pooling partials
    __shared__ float  spool[16][96];     // per-warp (half-sample) sums
    __shared__ float  sinv[8];
    __shared__ float  sin_[8][96];       // pooled inputs
    __shared__ float  actA[8][256];
    __shared__ float  actB[8][128];
    __shared__ float  sstat[8][2];
    __shared__ float  scoarse[8][3];

    const int tid = threadIdx.x, lane = tid & 31, w = tid >> 5;

    if (tid < 8) sidx[tid] = g_order[base + min(tid, cnt - 1)];
    __syncthreads();

    // ================= phase 1: pooling (2 warps per sample) ================
    {
        const int p = w >> 1, h = w & 1;
        const int b = sidx[p];
        const int start = g_bound[b], end = g_bound[b + 1];
        const int nrows = end - start;
        if (h == 0 && lane == 0) sinv[p] = 1.f / fmaxf((float)nrows, 1.f);
        const int half0 = nrows >> 1;
        const int rlo = h ? half0 : 0;
        const int myn = h ? (nrows - half0) : half0;
        const float* fbase = feat + (size_t)(start + rlo) * 96;

        const int i0 = lane, i1 = lane + 32, i2 = lane + 64;
        const int ro0 = i0 / 24, ro1 = i1 / 24, ro2 = i2 / 24;
        const int co0 = 4 * (i0 % 24), co1 = 4 * (i1 % 24), co2 = 4 * (i2 % 24);
        const float* p0 = fbase + ro0 * 96 + co0;
        const float* p1 = fbase + ro1 * 96 + co1;
        const float* p2 = fbase + ro2 * 96 + co2;

        float4 a0 = make_float4(0.f, 0.f, 0.f, 0.f), a1 = a0, a2 = a0;
        int r0 = 0;
        for (; r0 + 16 <= myn; r0 += 16) {
            float4 v0 = *(const float4*)(p0 + (size_t)(r0 +  0) * 96);
            float4 v1 = *(const float4*)(p1 + (size_t)(r0 +  0) * 96);
            float4 v2 = *(const float4*)(p2 + (size_t)(r0 +  0) * 96);
            float4 v3 = *(const float4*)(p0 + (size_t)(r0 +  4) * 96);
            float4 v4 = *(const float4*)(p1 + (size_t)(r0 +  4) * 96);
            float4 v5 = *(const float4*)(p2 + (size_t)(r0 +  4) * 96);
            float4 v6 = *(const float4*)(p0 + (size_t)(r0 +  8) * 96);
            float4 v7 = *(const float4*)(p1 + (size_t)(r0 +  8) * 96);
            float4 v8 = *(const float4*)(p2 + (size_t)(r0 +  8) * 96);
            float4 v9 = *(const float4*)(p0 + (size_t)(r0 + 12) * 96);
            float4 va = *(const float4*)(p1 + (size_t)(r0 + 12) * 96);
            float4 vb = *(const float4*)(p2 + (size_t)(r0 + 12) * 96);
            a0.x += v0.x; a0.y += v0.y; a0.z += v0.z; a0.w += v0.w;
            a1.x += v1.x; a1.y += v1.y; a1.z += v1.z; a1.w += v1.w;
            a2.x += v2.x; a2.y += v2.y; a2.z += v2.z; a2.w += v2.w;
            a0.x += v3.x; a0.y += v3.y; a0.z += v3.z; a0.w += v3.w;
            a1.x += v4.x; a1.y += v4.y; a1.z += v4.z; a1.w += v4.w;
            a2.x += v5.x; a2.y += v5.y; a2.z += v5.z; a2.w += v5.w;
            a0.x += v6.x; a0.y += v6.y; a0.z += v6.z; a0.w += v6.w;
            a1.x += v7.x; a1.y += v7.y; a1.z += v7.z; a1.w += v7.w;
            a2.x += v8.x; a2.y += v8.y; a2.z += v8.z; a2.w += v8.w;
            a0.x += v9.x; a0.y += v9.y; a0.z += v9.z; a0.w += v9.w;
            a1.x += va.x; a1.y += va.y; a1.z += va.z; a1.w += va.w;
            a2.x += vb.x; a2.y += vb.y; a2.z += vb.z; a2.w += vb.w;
        }
        for (; r0 + 8 <= myn; r0 += 8) {
            float4 v0 = *(const float4*)(p0 + (size_t)r0 * 96);
            float4 v1 = *(const float4*)(p1 + (size_t)r0 * 96);
            float4 v2 = *(const float4*)(p2 + (size_t)r0 * 96);
            float4 v3 = *(const float4*)(p0 + (size_t)(r0 + 4) * 96);
            float4 v4 = *(const float4*)(p1 + (size_t)(r0 + 4) * 96);
            float4 v5 = *(const float4*)(p2 + (size_t)(r0 + 4) * 96);
            a0.x += v0.x; a0.y += v0.y; a0.z += v0.z; a0.w += v0.w;
            a1.x += v1.x; a1.y += v1.y; a1.z += v1.z; a1.w += v1.w;
            a2.x += v2.x; a2.y += v2.y; a2.z += v2.z; a2.w += v2.w;
            a0.x += v3.x; a0.y += v3.y; a0.z += v3.z; a0.w += v3.w;
            a1.x += v4.x; a1.y += v4.y; a1.z += v4.z; a1.w += v4.w;
            a2.x += v5.x; a2.y += v5.y; a2.z += v5.z; a2.w += v5.w;
        }
        for (; r0 < myn; r0 += 4) {
            if (r0 + ro0 < myn) {
                float4 v = *(const float4*)(p0 + (size_t)r0 * 96);
                a0.x += v.x; a0.y += v.y; a0.z += v.z; a0.w += v.w;
            }
            if (r0 + ro1 < myn) {
                float4 v = *(const float4*)(p1 + (size_t)r0 * 96);
                a1.x += v.x; a1.y += v.y; a1.z += v.z; a1.w += v.w;
            }
            if (r0 + ro2 < myn) {
                float4 v = *(const float4*)(p2 + (size_t)r0 * 96);
                a2.x += v.x; a2.y += v.y; a2.z += v.z; a2.w += v.w;
            }
        }
        spart[w][ro0][co0 >> 2] = a0;
        spart[w][ro1][co1 >> 2] = a1;
        spart[w][ro2][co2 >> 2] = a2;
        __syncwarp();

        const float* sp = (const float*)&spart[w][0][0];
#pragma unroll
        for (int j = 0; j < 3; j++) {
            int c = lane + j * 32;
            spool[w][c] = sp[c] + sp[96 + c] + sp[192 + c] + sp[288 + c];
        }
    }
    __syncthreads();

    for (int idx = tid; idx < 8 * 96; idx += 512) {
        int p = idx / 96, c = idx - 96 * p;
        sin_[p][c] = (spool[2 * p][c] + spool[2 * p + 1][c]) * sinv[p];
    }
    __syncthreads();

    // ================= coarse L1: 96 -> 256 (2 groups x 4 samples) =========
    const int f1 = tid & 255, g1 = tid >> 8;   // g1 in 0..1
    float acc[4];
    {
        const float bv = cb1[f1];
#pragma unroll
        for (int i = 0; i < 4; i++) acc[i] = bv;
        for (int c = 0; c < 96; c += 4) {
            float w0 = cW1[(c + 0) * 256 + f1];
            float w1 = cW1[(c + 1) * 256 + f1];
            float w2 = cW1[(c + 2) * 256 + f1];
            float w3 = cW1[(c + 3) * 256 + f1];
#pragma unroll
            for (int i = 0; i < 4; i++) {
                float4 x = *(const float4*)(&sin_[4 * g1 + i][c]);
                acc[i] = fmaf(x.x, w0, acc[i]);
                acc[i] = fmaf(x.y, w1, acc[i]);
                acc[i] = fmaf(x.z, w2, acc[i]);
                acc[i] = fmaf(x.w, w3, acc[i]);
            }
        }
#pragma unroll
        for (int i = 0; i < 4; i++) actA[4 * g1 + i][f1] = acc[i];
    }
    __syncthreads();
    if (w < 8) {   // LN stats over 256, warp w -> sample w
        float su = 0.f, sq = 0.f;
#pragma unroll
        for (int j = 0; j < 8; j++) {
            float x = actA[w][lane + 32 * j];
            su += x; sq = fmaf(x, x, sq);
        }
        su = warpSum(su); sq = warpSum(sq);
        if (lane == 0) {
            float m = su * (1.f / 256.f);
            sstat[w][0] = m;
            sstat[w][1] = rsqrtf(sq * (1.f / 256.f) - m * m + EPS);
        }
    }
    __syncthreads();
    {
        const float g = cg1[f1], e = cbe1[f1];
#pragma unroll
        for (int i = 0; i < 4; i++) {
            int s = 4 * g1 + i;
            actA[s][f1] = fmaxf(fmaf((acc[i] - sstat[s][0]) * sstat[s][1], g, e), 0.f);
        }
    }
    __syncthreads();

    // ================= coarse L2: 256 -> 128 (4 groups x 2 samples) ========
    const int f2 = tid & 127, g2 = tid >> 7;   // g2 in 0..3
    float acc2[2];
    {
        const float bv = cb2[f2];
        acc2[0] = bv; acc2[1] = bv;
        for (int c = 0; c < 256; c += 4) {
            float w0 = cW2[(c + 0) * 128 + f2];
            float w1 = cW2[(c + 1) * 128 + f2];
            float w2 = cW2[(c + 2) * 128 + f2];
            float w3 = cW2[(c + 3) * 128 + f2];
#pragma unroll
            for (int i = 0; i < 2; i++) {
                float4 x = *(const float4*)(&actA[2 * g2 + i][c]);
                acc2[i] = fmaf(x.x, w0, acc2[i]);
                acc2[i] = fmaf(x.y, w1, acc2[i]);
                acc2[i] = fmaf(x.z, w2, acc2[i]);
                acc2[i] = fmaf(x.w, w3, acc2[i]);
            }
        }
        actB[2 * g2 + 0][f2] = acc2[0];
        actB[2 * g2 + 1][f2] = acc2[1];
    }
    __syncthreads();
    if (w < 8) {   // LN stats over 128
        float su = 0.f, sq = 0.f;
#pragma unroll
        for (int j = 0; j < 4; j++) {
            float x = actB[w][lane + 32 * j];
            su += x; sq = fmaf(x, x, sq);
        }
        su = warpSum(su); sq = warpSum(sq);
        if (lane == 0) {
            float m = su * (1.f / 128.f);
            sstat[w][0] = m;
            sstat[w][1] = rsqrtf(sq * (1.f / 128.f) - m * m + EPS);
        }
    }
    __syncthreads();
    {
        const float g = cg2[f2], e = cbe2[f2];
#pragma unroll
        for (int i = 0; i < 2; i++) {
            int s = 2 * g2 + i;
            actB[s][f2] = fmaxf(fmaf((acc2[i] - sstat[s][0]) * sstat[s][1], g, e), 0.f);
        }
    }
    __syncthreads();

    // ====== coarse L3 (warps 0..7) + refine L1 (all threads) ======
    if (w < 8) {
        float q0 = 0.f, q1 = 0.f, q2 = 0.f;
#pragma unroll
        for (int t = 0; t < 4; t++) {
            int c = lane + 32 * t;
            float x = actB[w][c];
            q0 = fmaf(x, cW3[c * 3 + 0], q0);
            q1 = fmaf(x, cW3[c * 3 + 1], q1);
            q2 = fmaf(x, cW3[c * 3 + 2], q2);
        }
        q0 = warpSum(q0); q1 = warpSum(q1); q2 = warpSum(q2);
        if (lane == 0) {
            scoarse[w][0] = q0 + cb3[0];
            scoarse[w][1] = q1 + cb3[1];
            scoarse[w][2] = q2 + cb3[2];
        }
    }
    // refine L1: 96 -> 128 into actA (4 groups x 2 samples)
    {
        const float* W = rW1 + k * 96 * 128;
        const float bv = rb1[k * 128 + f2];
        acc2[0] = bv; acc2[1] = bv;
        for (int c = 0; c < 96; c += 4) {
            float w0 = W[(c + 0) * 128 + f2];
            float w1 = W[(c + 1) * 128 + f2];
            float w2 = W[(c + 2) * 128 + f2];
            float w3 = W[(c + 3) * 128 + f2];
#pragma unroll
            for (int i = 0; i < 2; i++) {
                float4 x = *(const float4*)(&sin_[2 * g2 + i][c]);
                acc2[i] = fmaf(x.x, w0, acc2[i]);
                acc2[i] = fmaf(x.y, w1, acc2[i]);
                acc2[i] = fmaf(x.z, w2, acc2[i]);
                acc2[i] = fmaf(x.w, w3, acc2[i]);
            }
        }
        actA[2 * g2 + 0][f2] = acc2[0];
        actA[2 * g2 + 1][f2] = acc2[1];
    }
    __syncthreads();
    if (w < 8) {   // LN stats over 128 (refine L1)
        float su = 0.f, sq = 0.f;
#pragma unroll
        for (int j = 0; j < 4; j++) {
            float x = actA[w][lane + 32 * j];
            su += x; sq = fmaf(x, x, sq);
        }
        su = warpSum(su); sq = warpSum(sq);
        if (lane == 0) {
            float m = su * (1.f / 128.f);
            sstat[w][0] = m;
            sstat[w][1] = rsqrtf(sq * (1.f / 128.f) - m * m + EPS);
        }
    }
    __syncthreads();
    {
        const float g = rg1[k * 128 + f2], e = rbe1[k * 128 + f2];
#pragma unroll
        for (int i = 0; i < 2; i++) {
            int s = 2 * g2 + i;
            actA[s][f2] = fmaxf(fmaf((acc2[i] - sstat[s][0]) * sstat[s][1], g, e), 0.f);
        }
    }
    __syncthreads();

    // ================= refine L2: 128 -> 64 (8 groups x 1 sample) ==========
    const int f3 = tid & 63, g3 = tid >> 6;    // g3 in 0..7
    float acc3;
    {
        const float* W = rW2 + k * 128 * 64;
        acc3 = rb2[k * 64 + f3];
        for (int c = 0; c < 128; c += 4) {
            float4 x = *(const float4*)(&actA[g3][c]);
            acc3 = fmaf(x.x, W[(c + 0) * 64 + f3], acc3);
            acc3 = fmaf(x.y, W[(c + 1) * 64 + f3], acc3);
            acc3 = fmaf(x.z, W[(c + 2) * 64 + f3], acc3);
            acc3 = fmaf(x.w, W[(c + 3) * 64 + f3], acc3);
        }
        actB[g3][f3] = acc3;
    }
    __syncthreads();
    if (w < 8) {   // LN stats over 64
        float x0 = actB[w][lane], x1 = actB[w][lane + 32];
        float su = warpSum(x0 + x1);
        float sq = warpSum(fmaf(x0, x0, x1 * x1));
        if (lane == 0) {
            float m = su * (1.f / 64.f);
            sstat[w][0] = m;
            sstat[w][1] = rsqrtf(sq * (1.f / 64.f) - m * m + EPS);
        }
    }
    __syncthreads();
    {
        const float g = rg2[k * 64 + f3], e = rbe2[k * 64 + f3];
        actB[g3][f3] = fmaxf(fmaf((acc3 - sstat[g3][0]) * sstat[g3][1], g, e), 0.f);
    }
    __syncthreads();

    // ================= refine L3: 64 -> 3, add coarse, write ===============
    if (w < 8) {
        const float* W3 = rW3 + k * 192;
        float q0 = 0.f, q1 = 0.f, q2 = 0.f;
#pragma unroll
        for (int t = 0; t < 2; t++) {
            int c = lane + 32 * t;
            float x = actB[w][c];
            q0 = fmaf(x, W3[c * 3 + 0], q0);
            q1 = fmaf(x, W3[c * 3 + 1], q1);
            q2 = fmaf(x, W3[c * 3 + 2], q2);
        }
        q0 = warpSum(q0); q1 = warpSum(q1); q2 = warpSum(q2);
        if (lane < 3 && w < cnt) {
            float q = (lane == 0) ? q0 : (lane == 1) ? q1 : q2;
            out[sidx[w] * 3 + lane] = scoarse[w][lane] + q + rb3[k * 3 + lane];
        }
    }
}

// ---------------- launch ----------------
extern "C" void kernel_launch(void* const* d_in, const int* in_sizes, int n_in,
                              void* d_out, int out_size) {
    const float* feat = (const float*)d_in[0];
    const int*   seg  = (const int*)d_in[1];
    const int*   cls  = (const int*)d_in[2];
    const int N = in_sizes[1];
    const int B = in_sizes[2];

    bounds_kernel<<<(N / 4 + 255) / 256, 256>>>(seg, N, B);
    group_kernel<<<1, 256>>>(cls, B);
    fused_kernel<<<MAXCTA, 512>>>(
        feat,
        (const float*)d_in[3],  (const float*)d_in[4],  (const float*)d_in[5],  (const float*)d_in[6],
        (const float*)d_in[7],  (const float*)d_in[8],  (const float*)d_in[9],  (const float*)d_in[10],
        (const float*)d_in[11], (const float*)d_in[12],
        (const float*)d_in[13], (const float*)d_in[14], (const float*)d_in[15], (const float*)d_in[16],
        (const float*)d_in[17], (const float*)d_in[18], (const float*)d_in[19], (const float*)d_in[20],
        (const float*)d_in[21], (const float*)d_in[22],
        (float*)d_out);
}

// round 8
// speedup vs baseline: 1.4212x; 1.2704x over previous
#include <cuda_runtime.h>
#include <cstdint>

// VoxelBracketPredictor_v2 — 2-kernel pipeline (R5 structure + cp.async pooling):
//  k0 bounds: segment boundaries (int4 scan of sorted segment_ids)
//  k1 fused:  CTA = 8 CONTIGUOUS samples, 256 threads. Warp pools its sample via
//             cp.async ring (3 x 4-row SMEM buffers -> huge in-flight depth,
//             DRAM-saturating), then coarse MLP CTA-cooperative + refinement
//             warp-per-sample. SMEM ring is aliased with MLP activations.

#define EPS 1e-5f
#define BMAX 4096

__device__ int g_bound[BMAX + 1];

// ---------------- kernel 0: boundaries ----------------
__global__ void bounds_kernel(const int* __restrict__ seg, int N, int B) {
    int t = blockIdx.x * blockDim.x + threadIdx.x;
    int i = t * 4;
    if (i >= N) return;
    int vals[4];
    if (i + 4 <= N) {
        int4 v = *(const int4*)(seg + i);
        vals[0] = v.x; vals[1] = v.y; vals[2] = v.z; vals[3] = v.w;
    } else {
        for (int j = 0; j < 4; j++) vals[j] = (i + j < N) ? seg[i + j] : vals[j > 0 ? j - 1 : 0];
    }
    int prev = (i == 0) ? -1 : seg[i - 1];
    int lim = min(4, N - i);
    for (int j = 0; j < lim; j++) {
        int cur = vals[j];
        for (int b = prev + 1; b <= cur; b++) g_bound[b] = i + j;
        prev = cur;
    }
    if (i + 4 >= N)
        for (int b = prev + 1; b <= B; b++) g_bound[b] = N;
}

__device__ __forceinline__ float warpSum(float v) {
#pragma unroll
    for (int o = 16; o; o >>= 1) v += __shfl_xor_sync(0xffffffffu, v, o);
    return v;
}

__device__ __forceinline__ uint32_t smem_u32(const void* p) {
    uint32_t a;
    asm("{ .reg .u64 t; cvta.to.shared.u64 t, %1; cvt.u32.u64 %0, t; }" : "=r"(a) : "l"(p));
    return a;
}
__device__ __forceinline__ void cp_async16(uint32_t saddr, const void* gaddr) {
    asm volatile("cp.async.cg.shared.global [%0], [%1], 16;" :: "r"(saddr), "l"(gaddr));
}
#define CP_COMMIT() asm volatile("cp.async.commit_group;" ::)
#define CP_WAIT(n)  asm volatile("cp.async.wait_group %0;" :: "n"(n))

// ---------------- kernel 1: fused pool + MLP ----------------
// SMEM ring: per warp 3 buffers x 4 rows x 96 floats (1536 B each).
// ring region (9216 floats = 36 KB) is reused as actA(8x256)+actB(8x128) in MLP phase.
__global__ __launch_bounds__(256) void fused_kernel(
    const float* __restrict__ feat, const int* __restrict__ cls,
    const float* __restrict__ cW1, const float* __restrict__ cb1,
    const float* __restrict__ cg1, const float* __restrict__ cbe1,
    const float* __restrict__ cW2, const float* __restrict__ cb2,
    const float* __restrict__ cg2, const float* __restrict__ cbe2,
    const float* __restrict__ cW3, const float* __restrict__ cb3,
    const float* __restrict__ rW1, const float* __restrict__ rb1,
    const float* __restrict__ rg1, const float* __restrict__ rbe1,
    const float* __restrict__ rW2, const float* __restrict__ rb2,
    const float* __restrict__ rg2, const float* __restrict__ rbe2,
    const float* __restrict__ rW3, const float* __restrict__ rb3,
    float* __restrict__ out, int B)
{
    __shared__ float smem_all[9216];     // pool ring (8 warps x 3 x 384) / MLP acts
    __shared__ float sin_[8][96];        // pooled inputs
    __shared__ float sstat[8][2];

    const int tid = threadIdx.x, lane = tid & 31, w = tid >> 5;
    const int b = blockIdx.x * 8 + w;
    const bool valid = b < B;
    const int bc = valid ? b : B - 1;

    // ================= phase 1: cp.async mean pool (warp per sample) ========
    {
        const int start = g_bound[bc], end = g_bound[bc + 1];
        const int nr = end - start;
        const float* gsrc = feat + (size_t)start * 96;
        float* sb = smem_all + w * 1152;             // 3 bufs x 384 floats
        const uint32_t sb_u = smem_u32(sb);

        const int T = (nr + 3) >> 2;                 // 4-row chunks
        float a0 = 0.f, a1 = 0.f, a2 = 0.f;

        // issue chunk i into buffer i%3 (lane copies float4 slots lane, lane+32, lane+64)
        #define ISSUE(i)                                                              \
        {                                                                             \
            const int _i = (i);                                                       \
            const int _cnt = min(4, nr - _i * 4) * 24;   /* float4 count */           \
            const uint32_t _sbase = sb_u + (uint32_t)(_i % 3) * 1536u;                \
            const float* _g = gsrc + (size_t)_i * 384;                                \
            if (lane < _cnt)      cp_async16(_sbase + lane * 16u,        _g + lane * 4);        \
            if (lane + 32 < _cnt) cp_async16(_sbase + (lane + 32) * 16u, _g + (lane + 32) * 4); \
            if (lane + 64 < _cnt) cp_async16(_sbase + (lane + 64) * 16u, _g + (lane + 64) * 4); \
            CP_COMMIT();                                                              \
        }

        if (T > 0) ISSUE(0);
        if (T > 1) ISSUE(1);
        if (T > 2) ISSUE(2);

        for (int i = 0; i < T; i++) {
            const int after = T - 1 - i;
            if (after >= 2)      CP_WAIT(2);
            else if (after == 1) CP_WAIT(1);
            else                 CP_WAIT(0);
            __syncwarp();

            const float* bp = sb + (i % 3) * 384;
            const int rows = min(4, nr - i * 4);
            if (rows == 4) {
#pragma unroll
                for (int r = 0; r < 4; r++) {
                    a0 += bp[r * 96 + lane];
                    a1 += bp[r * 96 + 32 + lane];
                    a2 += bp[r * 96 + 64 + lane];
                }
            } else {
                for (int r = 0; r < rows; r++) {
                    a0 += bp[r * 96 + lane];
                    a1 += bp[r * 96 + 32 + lane];
                    a2 += bp[r * 96 + 64 + lane];
                }
            }
            __syncwarp();
            if (i + 3 < T) ISSUE(i + 3);
        }
        #undef ISSUE

        const float inv = 1.f / fmaxf((float)nr, 1.f);
        sin_[w][lane]      = a0 * inv;
        sin_[w][lane + 32] = a1 * inv;
        sin_[w][lane + 64] = a2 * inv;
    }
    __syncthreads();

    // MLP activation aliases over the (now idle) ring region
    float* actA = smem_all;          // 8 x 256
    float* actB = smem_all + 2048;   // 8 x 128
    #define ACTA(s, f) actA[(s) * 256 + (f)]
    #define ACTB(s, f) actB[(s) * 128 + (f)]

    // ================= phase 2: coarse L1 (96 -> 256), CTA-cooperative =====
    float acc[8];
    {
        const int f = tid;
        const float bv = cb1[f];
#pragma unroll
        for (int s = 0; s < 8; s++) acc[s] = bv;
#pragma unroll 2
        for (int c = 0; c < 96; c += 4) {
            float w0 = cW1[(c + 0) * 256 + f];
            float w1 = cW1[(c + 1) * 256 + f];
            float w2 = cW1[(c + 2) * 256 + f];
            float w3 = cW1[(c + 3) * 256 + f];
#pragma unroll
            for (int s = 0; s < 8; s++) {
                float4 x = *(const float4*)(&sin_[s][c]);
                acc[s] = fmaf(x.x, w0, acc[s]);
                acc[s] = fmaf(x.y, w1, acc[s]);
                acc[s] = fmaf(x.z, w2, acc[s]);
                acc[s] = fmaf(x.w, w3, acc[s]);
            }
        }
#pragma unroll
        for (int s = 0; s < 8; s++) ACTA(s, f) = acc[s];
    }
    __syncthreads();
    {   // stats for sample w over 256 features
        float sum = 0.f, sq = 0.f;
#pragma unroll
        for (int j = 0; j < 8; j++) {
            float x = ACTA(w, lane + 32 * j);
            sum += x; sq = fmaf(x, x, sq);
        }
        sum = warpSum(sum); sq = warpSum(sq);
        if (lane == 0) {
            float m = sum * (1.f / 256.f);
            float v = sq * (1.f / 256.f) - m * m;
            sstat[w][0] = m; sstat[w][1] = rsqrtf(v + EPS);
        }
    }
    __syncthreads();
    {
        const int f = tid;
        const float g = cg1[f], e = cbe1[f];
#pragma unroll
        for (int s = 0; s < 8; s++) {
            float m = sstat[s][0], r = sstat[s][1];
            ACTA(s, f) = fmaxf(fmaf((acc[s] - m) * r, g, e), 0.f);
        }
    }
    __syncthreads();

    // ================= phase 3: coarse L2 (256 -> 128), CTA-cooperative ====
    float acc2[4];
    const int fL2 = tid & 127, sh = tid >> 7;
    {
        const float bv = cb2[fL2];
#pragma unroll
        for (int i = 0; i < 4; i++) acc2[i] = bv;
#pragma unroll 2
        for (int c = 0; c < 256; c += 4) {
            float w0 = cW2[(c + 0) * 128 + fL2];
            float w1 = cW2[(c + 1) * 128 + fL2];
            float w2 = cW2[(c + 2) * 128 + fL2];
            float w3 = cW2[(c + 3) * 128 + fL2];
#pragma unroll
            for (int i = 0; i < 4; i++) {
                float4 x = *(const float4*)(&ACTA(sh * 4 + i, c));
                acc2[i] = fmaf(x.x, w0, acc2[i]);
                acc2[i] = fmaf(x.y, w1, acc2[i]);
                acc2[i] = fmaf(x.z, w2, acc2[i]);
                acc2[i] = fmaf(x.w, w3, acc2[i]);
            }
        }
#pragma unroll
        for (int i = 0; i < 4; i++) ACTB(sh * 4 + i, fL2) = acc2[i];
    }
    __syncthreads();
    {   // stats for sample w over 128 features
        float sum = 0.f, sq = 0.f;
#pragma unroll
        for (int j = 0; j < 4; j++) {
            float x = ACTB(w, lane + 32 * j);
            sum += x; sq = fmaf(x, x, sq);
        }
        sum = warpSum(sum); sq = warpSum(sq);
        if (lane == 0) {
            float m = sum * (1.f / 128.f);
            float v = sq * (1.f / 128.f) - m * m;
            sstat[w][0] = m; sstat[w][1] = rsqrtf(v + EPS);
        }
    }
    __syncthreads();
    {
        const float g = cg2[fL2], e = cbe2[fL2];
#pragma unroll
        for (int i = 0; i < 4; i++) {
            int s = sh * 4 + i;
            float m = sstat[s][0], r = sstat[s][1];
            ACTB(s, fL2) = fmaxf(fmaf((acc2[i] - m) * r, g, e), 0.f);
        }
    }
    __syncthreads();

    // ================= phase 4: warp-per-sample — coarse L3 + refinement ===
    float p0 = 0.f, p1 = 0.f, p2 = 0.f;
#pragma unroll
    for (int t = 0; t < 4; t++) {
        int c = lane + 32 * t;
        float x = ACTB(w, c);
        p0 = fmaf(x, cW3[c * 3 + 0], p0);
        p1 = fmaf(x, cW3[c * 3 + 1], p1);
        p2 = fmaf(x, cW3[c * 3 + 2], p2);
    }
    p0 = warpSum(p0) + cb3[0];
    p1 = warpSum(p1) + cb3[1];
    p2 = warpSum(p2) + cb3[2];

    const int k = cls[bc];
    const int f4 = lane * 4, f2 = lane * 2;

    // refine L1: 96 -> 128, LN, ReLU
    {
        const float* W = rW1 + k * 96 * 128;
        float4 bb = *(const float4*)(rb1 + k * 128 + f4);
        float B0[4] = {bb.x, bb.y, bb.z, bb.w};
#pragma unroll 2
        for (int c = 0; c < 96; c += 4) {
            float4 x = *(const float4*)(&sin_[w][c]);
            float4 wv;
            wv = *(const float4*)(W + (c + 0) * 128 + f4);
            B0[0] = fmaf(x.x, wv.x, B0[0]); B0[1] = fmaf(x.x, wv.y, B0[1]);
            B0[2] = fmaf(x.x, wv.z, B0[2]); B0[3] = fmaf(x.x, wv.w, B0[3]);
            wv = *(const float4*)(W + (c + 1) * 128 + f4);
            B0[0] = fmaf(x.y, wv.x, B0[0]); B0[1] = fmaf(x.y, wv.y, B0[1]);
            B0[2] = fmaf(x.y, wv.z, B0[2]); B0[3] = fmaf(x.y, wv.w, B0[3]);
            wv = *(const float4*)(W + (c + 2) * 128 + f4);
            B0[0] = fmaf(x.z, wv.x, B0[0]); B0[1] = fmaf(x.z, wv.y, B0[1]);
            B0[2] = fmaf(x.z, wv.z, B0[2]); B0[3] = fmaf(x.z, wv.w, B0[3]);
            wv = *(const float4*)(W + (c + 3) * 128 + f4);
            B0[0] = fmaf(x.w, wv.x, B0[0]); B0[1] = fmaf(x.w, wv.y, B0[1]);
            B0[2] = fmaf(x.w, wv.z, B0[2]); B0[3] = fmaf(x.w, wv.w, B0[3]);
        }
        float m = warpSum(B0[0] + B0[1] + B0[2] + B0[3]) * (1.f / 128.f);
        float v = 0.f;
#pragma unroll
        for (int j = 0; j < 4; j++) { float d = B0[j] - m; v = fmaf(d, d, v); }
        float r = rsqrtf(warpSum(v) * (1.f / 128.f) + EPS);
        float4 g = *(const float4*)(rg1 + k * 128 + f4);
        float4 e = *(const float4*)(rbe1 + k * 128 + f4);
        float4 o;
        o.x = fmaxf(fmaf((B0[0] - m) * r, g.x, e.x), 0.f);
        o.y = fmaxf(fmaf((B0[1] - m) * r, g.y, e.y), 0.f);
        o.z = fmaxf(fmaf((B0[2] - m) * r, g.z, e.z), 0.f);
        o.w = fmaxf(fmaf((B0[3] - m) * r, g.w, e.w), 0.f);
        *(float4*)(&ACTA(w, f4)) = o;
    }
    __syncwarp();

    // refine L2: 128 -> 64, LN, ReLU
    {
        const float* W = rW2 + k * 128 * 64;
        float2 bb = *(const float2*)(rb2 + k * 64 + f2);
        float D0[2] = {bb.x, bb.y};
#pragma unroll 2
        for (int c = 0; c < 128; c += 4) {
            float4 x = *(const float4*)(&ACTA(w, c));
            float2 wv;
            wv = *(const float2*)(W + (c + 0) * 64 + f2);
            D0[0] = fmaf(x.x, wv.x, D0[0]); D0[1] = fmaf(x.x, wv.y, D0[1]);
            wv = *(const float2*)(W + (c + 1) * 64 + f2);
            D0[0] = fmaf(x.y, wv.x, D0[0]); D0[1] = fmaf(x.y, wv.y, D0[1]);
            wv = *(const float2*)(W + (c + 2) * 64 + f2);
            D0[0] = fmaf(x.z, wv.x, D0[0]); D0[1] = fmaf(x.z, wv.y, D0[1]);
            wv = *(const float2*)(W + (c + 3) * 64 + f2);
            D0[0] = fmaf(x.w, wv.x, D0[0]); D0[1] = fmaf(x.w, wv.y, D0[1]);
        }
        float m = warpSum(D0[0] + D0[1]) * (1.f / 64.f);
        float d0 = D0[0] - m, d1 = D0[1] - m;
        float r = rsqrtf(warpSum(d0 * d0 + d1 * d1) * (1.f / 64.f) + EPS);
        float2 g = *(const float2*)(rg2 + k * 64 + f2);
        float2 e = *(const float2*)(rbe2 + k * 64 + f2);
        float2 o;
        o.x = fmaxf(fmaf(d0 * r, g.x, e.x), 0.f);
        o.y = fmaxf(fmaf(d1 * r, g.y, e.y), 0.f);
        *(float2*)(&ACTB(w, f2)) = o;
    }
    __syncwarp();

    // refine L3: 64 -> 3, add coarse, write out
    {
        const float* W3 = rW3 + k * 192;
        float q0 = 0.f, q1 = 0.f, q2 = 0.f;
#pragma unroll
        for (int t = 0; t < 2; t++) {
            int c = lane + 32 * t;
            float x = ACTB(w, c);
            q0 = fmaf(x, W3[c * 3 + 0], q0);
            q1 = fmaf(x, W3[c * 3 + 1], q1);
            q2 = fmaf(x, W3[c * 3 + 2], q2);
        }
        q0 = warpSum(q0) + rb3[k * 3 + 0];
        q1 = warpSum(q1) + rb3[k * 3 + 1];
        q2 = warpSum(q2) + rb3[k * 3 + 2];

        if (valid && lane < 3) {
            float pc = (lane == 0) ? p0 : (lane == 1) ? p1 : p2;
            float qc = (lane == 0) ? q0 : (lane == 1) ? q1 : q2;
            out[b * 3 + lane] = pc + qc;
        }
    }
    #undef ACTA
    #undef ACTB
}

// ---------------- launch ----------------
extern "C" void kernel_launch(void* const* d_in, const int* in_sizes, int n_in,
                              void* d_out, int out_size) {
    const float* feat = (const float*)d_in[0];
    const int*   seg  = (const int*)d_in[1];
    const int*   cls  = (const int*)d_in[2];
    const int N = in_sizes[1];
    const int B = in_sizes[2];

    bounds_kernel<<<(N / 4 + 255) / 256, 256>>>(seg, N, B);
    fused_kernel<<<(B + 7) / 8, 256>>>(
        feat, cls,
        (const float*)d_in[3],  (const float*)d_in[4],  (const float*)d_in[5],  (const float*)d_in[6],
        (const float*)d_in[7],  (const float*)d_in[8],  (const float*)d_in[9],  (const float*)d_in[10],
        (const float*)d_in[11], (const float*)d_in[12],
        (const float*)d_in[13], (const float*)d_in[14], (const float*)d_in[15], (const float*)d_in[16],
        (const float*)d_in[17], (const float*)d_in[18], (const float*)d_in[19], (const float*)d_in[20],
        (const float*)d_in[21], (const float*)d_in[22],
        (float*)d_out, B);
}